// round 16
// baseline (speedup 1.0000x reference)
#include <cuda_runtime.h>
#include <math.h>
#include <stdint.h>

// Problem constants
#define BATCH 4
#define SEQ   2048
#define DMODEL 1024
#define NHEAD 16
#define DHEAD 64
#define MTOT  (BATCH * SEQ)
#define WELEM (DMODEL * DMODEL)
// attention scale folded with log2(e): softmax computed in log2 domain
#define QSCALE (0.125f * 1.4426950408889634f)

// ---------------------------------------------------------------------------
// Scratch (device globals). q/k/v/attn hold tf32 BIT PATTERNS (uint32).
// ---------------------------------------------------------------------------
__device__ uint32_t g_q[(size_t)MTOT * DMODEL];
__device__ uint32_t g_k[(size_t)MTOT * DMODEL];
__device__ uint32_t g_v[(size_t)MTOT * DMODEL];
__device__ uint32_t g_at[(size_t)MTOT * DMODEL];
__device__ uint32_t g_xt[(size_t)MTOT * DMODEL];
__device__ uint32_t g_wt[(size_t)4 * WELEM];

__device__ __forceinline__ uint32_t f2tf32(float x) {
    uint32_t u;
    asm("cvt.rna.tf32.f32 %0, %1;" : "=r"(u) : "f"(x));
    return u;
}

__device__ __forceinline__ float ex2(float x) {
    float y;
    asm("ex2.approx.ftz.f32 %0, %1;" : "=f"(y) : "f"(x));
    return y;
}

__device__ __forceinline__ void mma_tf32(float c[4], const uint32_t a[4],
                                         uint32_t b0, uint32_t b1) {
    asm volatile(
        "mma.sync.aligned.m16n8k8.row.col.f32.tf32.tf32.f32 "
        "{%0,%1,%2,%3}, {%4,%5,%6,%7}, {%8,%9}, {%0,%1,%2,%3};\n"
        : "+f"(c[0]), "+f"(c[1]), "+f"(c[2]), "+f"(c[3])
        : "r"(a[0]), "r"(a[1]), "r"(a[2]), "r"(a[3]), "r"(b0), "r"(b1));
}

// ---------------------------------------------------------------------------
// fp32 -> tf32-bits conversion kernels
// ---------------------------------------------------------------------------
__global__ __launch_bounds__(256)
void conv_tf32_kernel(const float* __restrict__ in, uint32_t* __restrict__ out)
{
    size_t i = ((size_t)blockIdx.x * 256 + threadIdx.x) * 4;
    float4 v = *(const float4*)&in[i];
    *(uint4*)&out[i] = make_uint4(f2tf32(v.x), f2tf32(v.y), f2tf32(v.z), f2tf32(v.w));
}

__global__ __launch_bounds__(256)
void conv_w_kernel(const float* __restrict__ w0, const float* __restrict__ w1,
                   const float* __restrict__ w2, const float* __restrict__ w3)
{
    const float* src = (blockIdx.z == 0) ? w0 : (blockIdx.z == 1) ? w1
                     : (blockIdx.z == 2) ? w2 : w3;
    size_t i = ((size_t)blockIdx.x * 256 + threadIdx.x) * 4;
    float4 v = *(const float4*)&src[i];
    *(uint4*)&g_wt[(size_t)blockIdx.z * WELEM + i] =
        make_uint4(f2tf32(v.x), f2tf32(v.y), f2tf32(v.z), f2tf32(v.w));
}

// ---------------------------------------------------------------------------
// TF32 GEMM on tf32-bit inputs:  C = A @ W^T
// BLOCK TILE 128x256, 512 THREADS = 16 warps in 2m x 8n, warp tile 64x32,
// K-tile 32, 3-stage cp.async pipeline (166 KB smem, 1 CTA/SM, 16 warps/SM).
// Row stride 36 words (144B): 16B-aligned for cp.async; 36 = 4 mod 32 keeps
// fragment LDS conflict-free.
// ---------------------------------------------------------------------------
#define GKT   32
#define GSROW 36
#define GA_U32 (128 * GSROW)                        // 4608 words / stage
#define GB_U32 (256 * GSROW)                        // 9216 words / stage
#define GEMM_SMEM_BYTES (3 * (GA_U32 + GB_U32) * 4) // 165888 B

template<bool CVT>
__device__ __forceinline__
void gemm_body(uint32_t* smem, const uint32_t* __restrict__ A,
               const uint32_t* __restrict__ W, float* __restrict__ C,
               uint32_t* __restrict__ Ct, float oscale,
               int M, int N, int K, int bm, int bn)
{
    uint32_t* As = smem;                    // [3][128*GSROW]
    uint32_t* Bs = smem + 3 * GA_U32;       // [3][256*GSROW]

    const int tid = threadIdx.x;
    const int lane = tid & 31;
    const int warp = tid >> 5;              // 0..15
    const int wm = (warp >> 3) * 64;        // 0 or 64
    const int wn = (warp & 7) * 32;         // 0,32,...,224
    const int r = lane >> 2;
    const int qq = lane & 3;

    const uint32_t s_as = (uint32_t)__cvta_generic_to_shared(As);
    const uint32_t s_bs = (uint32_t)__cvta_generic_to_shared(Bs);

    float c[4][4][4];
#pragma unroll
    for (int i = 0; i < 4; i++)
#pragma unroll
        for (int j = 0; j < 4; j++)
#pragma unroll
            for (int x = 0; x < 4; x++) c[i][j][x] = 0.f;

    const int NT = K / GKT;                 // 32

    auto cp_tile = [&](int kt, int buf) {
        const int k0 = kt * GKT;
        const uint32_t abase = s_as + (uint32_t)(buf * GA_U32) * 4u;
        const uint32_t bbase = s_bs + (uint32_t)(buf * GB_U32) * 4u;
#pragma unroll
        for (int l = 0; l < 2; l++) {           // A: 128 rows x 8 float4 = 1024
            int idx = tid + l * 512;
            int rr = idx >> 3;
            int c4 = (idx & 7) * 4;
            uint32_t da = abase + (uint32_t)(rr * GSROW + c4) * 4u;
            const uint32_t* ga = &A[(size_t)(bm + rr) * K + k0 + c4];
            asm volatile("cp.async.ca.shared.global [%0], [%1], 16;\n"
                         :: "r"(da), "l"(ga));
        }
#pragma unroll
        for (int l = 0; l < 4; l++) {           // B: 256 rows x 8 float4 = 2048
            int idx = tid + l * 512;
            int rr = idx >> 3;
            int c4 = (idx & 7) * 4;
            uint32_t db = bbase + (uint32_t)(rr * GSROW + c4) * 4u;
            const uint32_t* gb = &W[(size_t)(bn + rr) * K + k0 + c4];
            asm volatile("cp.async.ca.shared.global [%0], [%1], 16;\n"
                         :: "r"(db), "l"(gb));
        }
        asm volatile("cp.async.commit_group;\n" ::: "memory");
    };

    cp_tile(0, 0);
    cp_tile(1, 1);

    for (int kt = 0; kt < NT; kt++) {
        if (kt + 1 < NT)
            asm volatile("cp.async.wait_group 1;\n" ::: "memory");
        else
            asm volatile("cp.async.wait_group 0;\n" ::: "memory");
        __syncthreads();
        if (kt + 2 < NT) {
            int b2 = kt + 2;
            cp_tile(b2, b2 % 3);
        }

        const uint32_t* as = As + (kt % 3) * GA_U32;
        const uint32_t* bs = Bs + (kt % 3) * GB_U32;

#pragma unroll
        for (int s = 0; s < 4; s++) {
            const int kb = s * 8 + qq;
            uint32_t a[4][4], b[4][2];
#pragma unroll
            for (int i = 0; i < 4; i++) {
                const uint32_t* p = as + (wm + i * 16 + r) * GSROW + kb;
                a[i][0] = p[0];
                a[i][2] = p[4];
                const uint32_t* p8 = p + 8 * GSROW;
                a[i][1] = p8[0];
                a[i][3] = p8[4];
            }
#pragma unroll
            for (int j = 0; j < 4; j++) {
                const uint32_t* p = bs + (wn + j * 8 + r) * GSROW + kb;
                b[j][0] = p[0];
                b[j][1] = p[4];
            }
#pragma unroll
            for (int i = 0; i < 4; i++)
#pragma unroll
                for (int j = 0; j < 4; j++)
                    mma_tf32(c[i][j], a[i], b[j][0], b[j][1]);
        }
    }
    __syncthreads();

#pragma unroll
    for (int i = 0; i < 4; i++) {
#pragma unroll
        for (int j = 0; j < 4; j++) {
            int row = bm + wm + i * 16 + r;
            int col = bn + wn + j * 8 + qq * 2;
            if (CVT) {
                *(uint2*)&Ct[(size_t)row * N + col] =
                    make_uint2(f2tf32(c[i][j][0] * oscale), f2tf32(c[i][j][1] * oscale));
                *(uint2*)&Ct[(size_t)(row + 8) * N + col] =
                    make_uint2(f2tf32(c[i][j][2] * oscale), f2tf32(c[i][j][3] * oscale));
            } else {
                *(float2*)&C[(size_t)row * N + col] =
                    make_float2(c[i][j][0], c[i][j][1]);
                *(float2*)&C[(size_t)(row + 8) * N + col] =
                    make_float2(c[i][j][2], c[i][j][3]);
            }
        }
    }
}

// Fused Q/K/V projection. Q pre-scaled by QSCALE (attention scale * log2e).
__global__ __launch_bounds__(512, 1)
void gemm_qkv_kernel()
{
    extern __shared__ uint32_t smem[];
    const int z = blockIdx.z;
    uint32_t* Ct = (z == 0) ? g_q : (z == 1) ? g_k : g_v;
    float oscale = (z == 0) ? QSCALE : 1.0f;
    gemm_body<true>(smem, g_xt, g_wt + (size_t)z * WELEM, nullptr, Ct, oscale,
                    MTOT, DMODEL, DMODEL, blockIdx.y * 128, blockIdx.x * 256);
}

__global__ __launch_bounds__(512, 1)
void gemm_out_kernel(float* __restrict__ out)
{
    extern __shared__ uint32_t smem[];
    gemm_body<false>(smem, g_at, g_wt + (size_t)3 * WELEM, out, nullptr, 1.0f,
                     MTOT, DMODEL, DMODEL, blockIdx.y * 128, blockIdx.x * 256);
}

// ---------------------------------------------------------------------------
// Tensor-core causal flash attention (unchanged from best kernel).
// 256 threads = 8 warps, Q tile 128, KV tile 64, 3-stage cp.async pipeline,
// softmax in log2 domain, all data tf32 bits.
// ---------------------------------------------------------------------------
#define KSTR 68
#define VSTR 72
#define FLASH_SMEM ((3 * 64 * KSTR + 3 * 64 * VSTR) * 4)   // 107520 B

__global__ __launch_bounds__(256, 2)
void flash_mma_kernel(const uint32_t* __restrict__ Q, const uint32_t* __restrict__ K,
                      const uint32_t* __restrict__ V, uint32_t* __restrict__ O)
{
    extern __shared__ uint32_t sm[];
    uint32_t* KsB = sm;
    uint32_t* VsB = sm + 3 * 64 * KSTR;

    const int bh = blockIdx.y;
    const int b = bh >> 4;
    const int h = bh & 15;
    const int qb = gridDim.x - 1 - blockIdx.x;
    const int q0 = qb * 128;
    const int tid = threadIdx.x;
    const int lane = tid & 31;
    const int warp = tid >> 5;
    const int wm = warp * 16;
    const int r = lane >> 2;
    const int qq = lane & 3;

    const uint32_t* Qb = Q + ((size_t)b * SEQ) * DMODEL + h * DHEAD;
    const uint32_t* Kb = K + ((size_t)b * SEQ) * DMODEL + h * DHEAD;
    const uint32_t* Vb = V + ((size_t)b * SEQ) * DMODEL + h * DHEAD;

#pragma unroll
    for (int i = 0; i < 8; i++) {
        int idx = tid + i * 256;
        int rr = idx >> 4;
        int cc = (idx & 15) * 4;
        *(uint4*)&KsB[rr * KSTR + cc] = *(const uint4*)&Qb[(size_t)(q0 + rr) * DMODEL + cc];
    }
    __syncthreads();

    uint32_t qf[8][4];
#pragma unroll
    for (int kk = 0; kk < 8; kk++) {
        qf[kk][0] = KsB[(wm + r) * KSTR + kk * 8 + qq];
        qf[kk][1] = KsB[(wm + r + 8) * KSTR + kk * 8 + qq];
        qf[kk][2] = KsB[(wm + r) * KSTR + kk * 8 + qq + 4];
        qf[kk][3] = KsB[(wm + r + 8) * KSTR + kk * 8 + qq + 4];
    }
    __syncthreads();

    float o[8][4];
#pragma unroll
    for (int j = 0; j < 8; j++)
#pragma unroll
        for (int x = 0; x < 4; x++) o[j][x] = 0.f;
    float m0 = -INFINITY, m1 = -INFINITY;
    float l0 = 0.f, l1 = 0.f;

    const int base = lane & 28;
    const int sl0 = base + (qq >> 1);
    const int sl1 = sl0 + 2;
    const bool odd = (qq & 1);

    const int nt = 2 * qb + 2;
    const uint32_t s_k = (uint32_t)__cvta_generic_to_shared(KsB);
    const uint32_t s_v = (uint32_t)__cvta_generic_to_shared(VsB);

    auto cp_tile = [&](int t, int buf) {
        const int k0 = t * 64;
        const uint32_t kb = s_k + (uint32_t)(buf * 64 * KSTR) * 4u;
        const uint32_t vb = s_v + (uint32_t)(buf * 64 * VSTR) * 4u;
#pragma unroll
        for (int l = 0; l < 4; l++) {
            int idx = tid + l * 256;
            int rr = idx >> 4;
            int cc = (idx & 15) * 4;
            uint32_t dk = kb + (uint32_t)(rr * KSTR + cc) * 4u;
            const uint32_t* gk = &Kb[(size_t)(k0 + rr) * DMODEL + cc];
            asm volatile("cp.async.ca.shared.global [%0], [%1], 16;\n"
                         :: "r"(dk), "l"(gk));
            uint32_t dv = vb + (uint32_t)(rr * VSTR + cc) * 4u;
            const uint32_t* gv = &Vb[(size_t)(k0 + rr) * DMODEL + cc];
            asm volatile("cp.async.ca.shared.global [%0], [%1], 16;\n"
                         :: "r"(dv), "l"(gv));
        }
        asm volatile("cp.async.commit_group;\n" ::: "memory");
    };

    cp_tile(0, 0);
    if (nt > 1) cp_tile(1, 1);

    for (int t = 0; t < nt; t++) {
        if (t + 1 < nt)
            asm volatile("cp.async.wait_group 1;\n" ::: "memory");
        else
            asm volatile("cp.async.wait_group 0;\n" ::: "memory");
        __syncthreads();
        if (t + 2 < nt) cp_tile(t + 2, (t + 2) % 3);

        const uint32_t* ks = KsB + (t % 3) * 64 * KSTR;
        const uint32_t* vs = VsB + (t % 3) * 64 * VSTR;
        const int k0 = t * 64;

        if (k0 <= q0 + wm + 15) {
            float cf[8][4];
#pragma unroll
            for (int j = 0; j < 8; j++) {
#pragma unroll
                for (int x = 0; x < 4; x++) cf[j][x] = 0.f;
#pragma unroll
                for (int kk = 0; kk < 8; kk++) {
                    uint32_t b0 = ks[(j * 8 + r) * KSTR + kk * 8 + qq];
                    uint32_t b1 = ks[(j * 8 + r) * KSTR + kk * 8 + qq + 4];
                    mma_tf32(cf[j], qf[kk], b0, b1);
                }
            }

            if (t >= nt - 2) {
                const int row0 = q0 + wm + r;
                const int row1 = row0 + 8;
#pragma unroll
                for (int j = 0; j < 8; j++) {
                    int kc = k0 + j * 8 + 2 * qq;
                    if (kc > row0)     cf[j][0] = -INFINITY;
                    if (kc + 1 > row0) cf[j][1] = -INFINITY;
                    if (kc > row1)     cf[j][2] = -INFINITY;
                    if (kc + 1 > row1) cf[j][3] = -INFINITY;
                }
            }

            float t0 = -INFINITY, t1 = -INFINITY;
#pragma unroll
            for (int j = 0; j < 8; j++) {
                t0 = fmaxf(t0, fmaxf(cf[j][0], cf[j][1]));
                t1 = fmaxf(t1, fmaxf(cf[j][2], cf[j][3]));
            }
            t0 = fmaxf(t0, __shfl_xor_sync(0xffffffffu, t0, 1));
            t0 = fmaxf(t0, __shfl_xor_sync(0xffffffffu, t0, 2));
            t1 = fmaxf(t1, __shfl_xor_sync(0xffffffffu, t1, 1));
            t1 = fmaxf(t1, __shfl_xor_sync(0xffffffffu, t1, 2));

            float nm0 = fmaxf(m0, t0);
            float nm1 = fmaxf(m1, t1);
            float alpha0 = ex2(m0 - nm0);
            float alpha1 = ex2(m1 - nm1);
            m0 = nm0; m1 = nm1;

            float rs0 = 0.f, rs1 = 0.f;
#pragma unroll
            for (int j = 0; j < 8; j++) {
                cf[j][0] = ex2(cf[j][0] - m0); rs0 += cf[j][0];
                cf[j][1] = ex2(cf[j][1] - m0); rs0 += cf[j][1];
                cf[j][2] = ex2(cf[j][2] - m1); rs1 += cf[j][2];
                cf[j][3] = ex2(cf[j][3] - m1); rs1 += cf[j][3];
            }
            rs0 += __shfl_xor_sync(0xffffffffu, rs0, 1);
            rs0 += __shfl_xor_sync(0xffffffffu, rs0, 2);
            rs1 += __shfl_xor_sync(0xffffffffu, rs1, 1);
            rs1 += __shfl_xor_sync(0xffffffffu, rs1, 2);
            l0 = l0 * alpha0 + rs0;
            l1 = l1 * alpha1 + rs1;

#pragma unroll
            for (int j = 0; j < 8; j++) {
                o[j][0] *= alpha0; o[j][1] *= alpha0;
                o[j][2] *= alpha1; o[j][3] *= alpha1;
            }

#pragma unroll
            for (int kk = 0; kk < 8; kk++) {
                float v00 = __shfl_sync(0xffffffffu, cf[kk][0], sl0);
                float v01 = __shfl_sync(0xffffffffu, cf[kk][1], sl0);
                float v20 = __shfl_sync(0xffffffffu, cf[kk][0], sl1);
                float v21 = __shfl_sync(0xffffffffu, cf[kk][1], sl1);
                float v10 = __shfl_sync(0xffffffffu, cf[kk][2], sl0);
                float v11 = __shfl_sync(0xffffffffu, cf[kk][3], sl0);
                float v30 = __shfl_sync(0xffffffffu, cf[kk][2], sl1);
                float v31 = __shfl_sync(0xffffffffu, cf[kk][3], sl1);
                uint32_t pa[4];
                pa[0] = f2tf32(odd ? v01 : v00);
                pa[1] = f2tf32(odd ? v11 : v10);
                pa[2] = f2tf32(odd ? v21 : v20);
                pa[3] = f2tf32(odd ? v31 : v30);
#pragma unroll
                for (int j2 = 0; j2 < 8; j2++) {
                    uint32_t b0 = vs[(kk * 8 + qq) * VSTR + j2 * 8 + r];
                    uint32_t b1 = vs[(kk * 8 + qq + 4) * VSTR + j2 * 8 + r];
                    mma_tf32(o[j2], pa, b0, b1);
                }
            }
        }
        __syncthreads();
    }

    const float inv0 = 1.f / l0;
    const float inv1 = 1.f / l1;
    uint32_t* Ob = O + ((size_t)b * SEQ) * DMODEL + h * DHEAD;
    const int row0 = q0 + wm + r;
#pragma unroll
    for (int j2 = 0; j2 < 8; j2++) {
        int col = j2 * 8 + 2 * qq;
        *(uint2*)&Ob[(size_t)row0 * DMODEL + col] =
            make_uint2(f2tf32(o[j2][0] * inv0), f2tf32(o[j2][1] * inv0));
        *(uint2*)&Ob[(size_t)(row0 + 8) * DMODEL + col] =
            make_uint2(f2tf32(o[j2][2] * inv1), f2tf32(o[j2][3] * inv1));
    }
}

// ---------------------------------------------------------------------------
// Launch
// ---------------------------------------------------------------------------
extern "C" void kernel_launch(void* const* d_in, const int* in_sizes, int n_in,
                              void* d_out, int out_size)
{
    const float* x  = (const float*)d_in[0];
    const float* Wq = (const float*)d_in[1];
    const float* Wk = (const float*)d_in[2];
    const float* Wv = (const float*)d_in[3];
    const float* Wo = (const float*)d_in[4];
    float* out = (float*)d_out;

    uint32_t *q_ptr, *k_ptr, *v_ptr, *at_ptr, *xt_ptr;
    cudaGetSymbolAddress((void**)&q_ptr,  g_q);
    cudaGetSymbolAddress((void**)&k_ptr,  g_k);
    cudaGetSymbolAddress((void**)&v_ptr,  g_v);
    cudaGetSymbolAddress((void**)&at_ptr, g_at);
    cudaGetSymbolAddress((void**)&xt_ptr, g_xt);

    static int attr_set = 0;
    if (!attr_set) {
        cudaFuncSetAttribute(gemm_qkv_kernel,
                             cudaFuncAttributeMaxDynamicSharedMemorySize,
                             GEMM_SMEM_BYTES);
        cudaFuncSetAttribute(gemm_out_kernel,
                             cudaFuncAttributeMaxDynamicSharedMemorySize,
                             GEMM_SMEM_BYTES);
        cudaFuncSetAttribute(flash_mma_kernel,
                             cudaFuncAttributeMaxDynamicSharedMemorySize,
                             FLASH_SMEM);
        attr_set = 1;
    }

    // 1. pre-convert x and weights to tf32 bits
    conv_tf32_kernel<<<(MTOT * DMODEL) / (256 * 4), 256>>>(x, xt_ptr);
    conv_w_kernel<<<dim3(WELEM / (256 * 4), 1, 4), 256>>>(Wq, Wk, Wv, Wo);

    // 2. fused Q/K/V projections (outputs tf32 bits; Q pre-scaled)
    gemm_qkv_kernel<<<dim3(DMODEL / 256, MTOT / 128, 3), 512, GEMM_SMEM_BYTES>>>();

    // 3. flash attention (tf32 in, tf32 out)
    dim3 agrid(SEQ / 128, BATCH * NHEAD);   // (16, 64)
    flash_mma_kernel<<<agrid, 256, FLASH_SMEM>>>(q_ptr, k_ptr, v_ptr, at_ptr);

    // 4. output projection
    gemm_out_kernel<<<dim3(DMODEL / 256, MTOT / 128), 512, GEMM_SMEM_BYTES>>>(out);
}